// round 4
// baseline (speedup 1.0000x reference)
#include <cuda_runtime.h>
#include <cuda_fp16.h>
#include <cstdint>

// Problem constants
#define NTOK 8192
#define INF  4096
#define OUTF 4096

// GEMM tiling
#define MT    128                // M tile
#define NTLE  256                // N tile
#define KCH   32                 // K chunk (halves)
#define STAGES 4
#define NCH   (INF / KCH)        // 128 chunks
#define ROWPITCH 80              // bytes per smem row (32 halves + 8 pad)
#define STG   ((MT + NTLE) * ROWPITCH)   // 30720 bytes per stage
#define SMEM_TOTAL (STAGES * STG)        // 122880

// Scratch (device globals: allocation-free rule)
__device__ __half g_wh[(size_t)OUTF * INF];   // W fp16 [o][k], atomicAdd target
__device__ __half g_xh[(size_t)NTOK * INF];   // x fp16 [m][k]
__device__ int    g_is64;

// ---------------------------------------------------------------------------
// PTX helpers (base sm_80-class: legal on plain sm_103 target)
__device__ __forceinline__ uint32_t s2u(const void* p) {
    uint32_t a;
    asm("{ .reg .u64 t; cvta.to.shared.u64 t, %1; cvt.u32.u64 %0, t; }"
        : "=r"(a) : "l"(p));
    return a;
}
#define CP_ASYNC16(smem, gptr) \
    asm volatile("cp.async.cg.shared.global [%0], [%1], 16;" :: "r"(smem), "l"(gptr))
#define CP_COMMIT() asm volatile("cp.async.commit_group;" ::: "memory")
#define CP_WAIT(n)  asm volatile("cp.async.wait_group %0;" :: "n"(n) : "memory")

__device__ __forceinline__ void ldsm4(uint32_t* r, uint32_t addr) {
    asm volatile("ldmatrix.sync.aligned.m8n8.x4.shared.b16 {%0,%1,%2,%3}, [%4];"
        : "=r"(r[0]), "=r"(r[1]), "=r"(r[2]), "=r"(r[3]) : "r"(addr));
}
__device__ __forceinline__ void mma16816(float* d, const uint32_t* a,
                                         uint32_t b0, uint32_t b1) {
    asm volatile(
        "mma.sync.aligned.m16n8k16.row.col.f32.f16.f16.f32 "
        "{%0,%1,%2,%3}, {%4,%5,%6,%7}, {%8,%9}, {%0,%1,%2,%3};"
        : "+f"(d[0]), "+f"(d[1]), "+f"(d[2]), "+f"(d[3])
        : "r"(a[0]), "r"(a[1]), "r"(a[2]), "r"(a[3]), "r"(b0), "r"(b1));
}

// ---------------------------------------------------------------------------
// Prep kernels
__global__ void k_detect(const int* __restrict__ idx32) {
    if (threadIdx.x == 0 && blockIdx.x == 0) {
        int z = 0;
        #pragma unroll
        for (int k = 1; k < 128; k += 2) z |= idx32[k];
        g_is64 = (z == 0) ? 1 : 0;
    }
}

__global__ void k_zero_wh() {
    size_t i = (size_t)blockIdx.x * blockDim.x + threadIdx.x;  // one uint4 = 8 halves
    ((uint4*)g_wh)[i] = make_uint4(0u, 0u, 0u, 0u);
}

__device__ __forceinline__ int load_idx(const void* idxv, long long pos) {
    if (g_is64) return (int)((const long long*)idxv)[pos];
    return ((const int*)idxv)[pos];
}

// Scatter straight into fp16 dense W (duplicates summed by atomicAdd)
__global__ void k_scatter(const void* __restrict__ idxv,
                          const float* __restrict__ w, int nnz) {
    int j = blockIdx.x * blockDim.x + threadIdx.x;
    if (j >= nnz) return;
    int o = load_idx(idxv, j);
    int c = load_idx(idxv, (long long)nnz + j);
    atomicAdd(&g_wh[(size_t)o * INF + c], __float2half(w[j]));
}

__global__ void k_conv_x(const float* __restrict__ x) {
    size_t i = (size_t)blockIdx.x * blockDim.x + threadIdx.x;  // one float4
    float4 f = ((const float4*)x)[i];
    __half2 a = __floats2half2_rn(f.x, f.y);
    __half2 b = __floats2half2_rn(f.z, f.w);
    uint2 v;
    v.x = *(uint32_t*)&a;
    v.y = *(uint32_t*)&b;
    ((uint2*)g_xh)[i] = v;
}

// ---------------------------------------------------------------------------
// GEMM: out[m][n] = sum_k xh[m][k] * wh[n][k] + bias[n]
// 256 threads = 8 warps (2 m-warps x 4 n-warps), warp tile 64x64.
// smem stage: rows 0..127 = A (m), rows 128..383 = B (n), pitch 80B.
__device__ __forceinline__ void load_stage(uint32_t sb, int s, int ch,
                                           int m0, int n0, int tid) {
    uint32_t stb = sb + s * STG;
    int kk = ch * KCH;
    #pragma unroll
    for (int i = 0; i < 6; i++) {
        int idx = tid + i * 256;          // 1536 x 16B chunks per stage
        int row = idx >> 2;
        int c   = idx & 3;
        uint32_t so = stb + row * ROWPITCH + c * 16;
        const __half* g;
        if (row < MT)
            g = &g_xh[(size_t)(m0 + row) * INF + kk + c * 8];
        else
            g = &g_wh[(size_t)(n0 + row - MT) * INF + kk + c * 8];
        CP_ASYNC16(so, g);
    }
}

__global__ void __launch_bounds__(256, 1) k_gemm(
    const float* __restrict__ bias, float* __restrict__ out)
{
    extern __shared__ char sm[];
    uint32_t sb = s2u(sm);
    int tid = threadIdx.x;
    int wid = tid >> 5, lane = tid & 31;
    int mw = wid >> 2, nw = wid & 3;      // 2x4 warp grid
    int m0 = blockIdx.y * MT;
    int n0 = blockIdx.x * NTLE;

    float acc[4][8][4];                   // 4 m-subtiles(16) x 8 n-subtiles(8)
    #pragma unroll
    for (int i = 0; i < 4; i++)
        #pragma unroll
        for (int j = 0; j < 8; j++)
            #pragma unroll
            for (int q = 0; q < 4; q++) acc[i][j][q] = 0.f;

    // per-thread ldmatrix base offsets (within a stage)
    uint32_t a_off = (uint32_t)(mw * 64 + (lane & 15)) * ROWPITCH + (lane >> 4) * 16;
    uint32_t b_off = (uint32_t)(MT + nw * 64 + (lane & 15)) * ROWPITCH + (lane >> 4) * 16;

    // prologue: stages 0..2
    #pragma unroll
    for (int s = 0; s < STAGES - 1; s++) {
        load_stage(sb, s, s, m0, n0, tid);
        CP_COMMIT();
    }

    #pragma unroll 1
    for (int ch = 0; ch < NCH; ch++) {
        CP_WAIT(STAGES - 2);
        __syncthreads();

        if (ch + STAGES - 1 < NCH)
            load_stage(sb, (ch + STAGES - 1) & (STAGES - 1), ch + STAGES - 1,
                       m0, n0, tid);
        CP_COMMIT();

        uint32_t stb = sb + (ch & (STAGES - 1)) * STG;
        uint32_t ab = stb + a_off;
        uint32_t bb = stb + b_off;
        #pragma unroll
        for (int ks = 0; ks < 2; ks++) {
            uint32_t a[4][4];
            #pragma unroll
            for (int im = 0; im < 4; im++)
                ldsm4(a[im], ab + im * 16 * ROWPITCH + ks * 32);
            #pragma unroll
            for (int j = 0; j < 4; j++) {
                uint32_t b[4];
                ldsm4(b, bb + j * 16 * ROWPITCH + ks * 32);
                #pragma unroll
                for (int im = 0; im < 4; im++) {
                    mma16816(acc[im][2 * j],     a[im], b[0], b[2]);
                    mma16816(acc[im][2 * j + 1], a[im], b[1], b[3]);
                }
            }
        }
    }

    // epilogue: add bias, store float2 pairs
    int l4 = lane >> 2;            // row 0..7 within 8
    int l2 = (lane & 3) * 2;       // col pair base
    #pragma unroll
    for (int im = 0; im < 4; im++) {
        int mbase = m0 + mw * 64 + im * 16 + l4;
        #pragma unroll
        for (int jn = 0; jn < 8; jn++) {
            int col = n0 + nw * 64 + jn * 8 + l2;
            float2 bv = *(const float2*)(bias + col);
            float2 v0, v1;
            v0.x = acc[im][jn][0] + bv.x;
            v0.y = acc[im][jn][1] + bv.y;
            v1.x = acc[im][jn][2] + bv.x;
            v1.y = acc[im][jn][3] + bv.y;
            *(float2*)(out + (size_t)mbase * OUTF + col) = v0;
            *(float2*)(out + (size_t)(mbase + 8) * OUTF + col) = v1;
        }
    }
}

// ---------------------------------------------------------------------------
extern "C" void kernel_launch(void* const* d_in, const int* in_sizes, int n_in,
                              void* d_out, int out_size) {
    const float* x    = (const float*)d_in[0];  // [8192, 4096] f32
    const float* w    = (const float*)d_in[1];  // [NNZ] f32
    const float* bias = (const float*)d_in[2];  // [4096] f32
    const void*  idx  = d_in[3];                // [2, NNZ] int64 or int32
    float* out = (float*)d_out;                 // [8192, 4096] f32
    int nnz = in_sizes[1];

    static bool attr_set = false;
    if (!attr_set) {
        cudaFuncSetAttribute(k_gemm, cudaFuncAttributeMaxDynamicSharedMemorySize,
                             SMEM_TOTAL);
        attr_set = true;
    }

    k_detect<<<1, 32>>>((const int*)idx);
    k_zero_wh<<<(int)((size_t)OUTF * INF / 8 / 256), 256>>>();
    k_scatter<<<(nnz + 255) / 256, 256>>>(idx, w, nnz);
    k_conv_x<<<(int)((size_t)NTOK * INF / 4 / 256), 256>>>(x);

    dim3 grid(OUTF / NTLE, NTOK / MT);   // (16, 64)
    k_gemm<<<grid, 256, SMEM_TOTAL>>>(bias, out);
}

// round 7
// speedup vs baseline: 1.0811x; 1.0811x over previous
#include <cuda_runtime.h>
#include <cuda_fp16.h>
#include <cstdint>

// Problem constants
#define NTOK 8192
#define INF  4096
#define OUTF 4096

// GEMM tiling (known-good R3 configuration)
#define MT    128                // M tile
#define NTLE  256                // N tile
#define KCH   32                 // K chunk (halves)
#define STAGES 4
#define NCH   (INF / KCH)        // 128 chunks
#define ROWPITCH 80              // bytes per smem row (32 halves + 8 pad)
#define STG   ((MT + NTLE) * ROWPITCH)   // 30720 bytes per stage
#define SMEM_TOTAL (STAGES * STG)        // 122880

// Scratch (device globals: allocation-free rule)
__device__ __half g_wh[(size_t)OUTF * INF];   // W fp16 [o][k], atomicAdd target
__device__ __half g_xh[(size_t)NTOK * INF];   // x fp16 [m][k]
__device__ int    g_is64;

// ---------------------------------------------------------------------------
// PTX helpers (base sm_80-class: legal on plain sm_103 target)
__device__ __forceinline__ uint32_t s2u(const void* p) {
    uint32_t a;
    asm("{ .reg .u64 t; cvta.to.shared.u64 t, %1; cvt.u32.u64 %0, t; }"
        : "=r"(a) : "l"(p));
    return a;
}
#define CP_ASYNC16(smem, gptr) \
    asm volatile("cp.async.cg.shared.global [%0], [%1], 16;" :: "r"(smem), "l"(gptr))
#define CP_COMMIT() asm volatile("cp.async.commit_group;" ::: "memory")
#define CP_WAIT(n)  asm volatile("cp.async.wait_group %0;" :: "n"(n) : "memory")

__device__ __forceinline__ void ldsm4(uint32_t* r, uint32_t addr) {
    asm volatile("ldmatrix.sync.aligned.m8n8.x4.shared.b16 {%0,%1,%2,%3}, [%4];"
        : "=r"(r[0]), "=r"(r[1]), "=r"(r[2]), "=r"(r[3]) : "r"(addr));
}
__device__ __forceinline__ void mma16816(float* d, const uint32_t* a,
                                         uint32_t b0, uint32_t b1) {
    asm volatile(
        "mma.sync.aligned.m16n8k16.row.col.f32.f16.f16.f32 "
        "{%0,%1,%2,%3}, {%4,%5,%6,%7}, {%8,%9}, {%0,%1,%2,%3};"
        : "+f"(d[0]), "+f"(d[1]), "+f"(d[2]), "+f"(d[3])
        : "r"(a[0]), "r"(a[1]), "r"(a[2]), "r"(a[3]), "r"(b0), "r"(b1));
}

// ---------------------------------------------------------------------------
// Prep kernels
__global__ void k_detect(const int* __restrict__ idx32) {
    if (threadIdx.x == 0 && blockIdx.x == 0) {
        int z = 0;
        #pragma unroll
        for (int k = 1; k < 128; k += 2) z |= idx32[k];
        g_is64 = (z == 0) ? 1 : 0;
    }
}

__global__ void k_zero_wh() {
    size_t i = (size_t)blockIdx.x * blockDim.x + threadIdx.x;  // one uint4 = 8 halves
    ((uint4*)g_wh)[i] = make_uint4(0u, 0u, 0u, 0u);
}

__device__ __forceinline__ int load_idx(const void* idxv, long long pos) {
    if (g_is64) return (int)((const long long*)idxv)[pos];
    return ((const int*)idxv)[pos];
}

// Scatter straight into fp16 dense W (duplicates summed by atomicAdd)
__global__ void k_scatter(const void* __restrict__ idxv,
                          const float* __restrict__ w, int nnz) {
    int j = blockIdx.x * blockDim.x + threadIdx.x;
    if (j >= nnz) return;
    int o = load_idx(idxv, j);
    int c = load_idx(idxv, (long long)nnz + j);
    atomicAdd(&g_wh[(size_t)o * INF + c], __float2half(w[j]));
}

__global__ void k_conv_x(const float* __restrict__ x) {
    size_t i = (size_t)blockIdx.x * blockDim.x + threadIdx.x;  // one float4
    float4 f = ((const float4*)x)[i];
    __half2 a = __floats2half2_rn(f.x, f.y);
    __half2 b = __floats2half2_rn(f.z, f.w);
    uint2 v;
    v.x = *(uint32_t*)&a;
    v.y = *(uint32_t*)&b;
    ((uint2*)g_xh)[i] = v;
}

// ---------------------------------------------------------------------------
// GEMM: out[m][n] = sum_k xh[m][k] * wh[n][k] + bias[n]
// 512 threads = 16 warps (4 m-warps x 4 n-warps), warp tile 32x64.
// smem stage: rows 0..127 = A (m), rows 128..383 = B (n), pitch 80B.
__device__ __forceinline__ void load_stage(uint32_t sb, int s, int ch,
                                           int m0, int n0, int tid) {
    uint32_t stb = sb + s * STG;
    int kk = ch * KCH;
    #pragma unroll
    for (int i = 0; i < 3; i++) {
        int idx = tid + i * 512;          // 1536 x 16B chunks per stage
        int row = idx >> 2;
        int c   = idx & 3;
        uint32_t so = stb + row * ROWPITCH + c * 16;
        const __half* g;
        if (row < MT)
            g = &g_xh[(size_t)(m0 + row) * INF + kk + c * 8];
        else
            g = &g_wh[(size_t)(n0 + row - MT) * INF + kk + c * 8];
        CP_ASYNC16(so, g);
    }
}

__global__ void __launch_bounds__(512, 1) k_gemm(
    const float* __restrict__ bias, float* __restrict__ out)
{
    extern __shared__ char sm[];
    uint32_t sb = s2u(sm);
    int tid = threadIdx.x;
    int wid = tid >> 5, lane = tid & 31;
    int mw = wid >> 2, nw = wid & 3;      // 4x4 warp grid
    int m0 = blockIdx.y * MT;
    int n0 = blockIdx.x * NTLE;

    float acc[2][8][4];
    #pragma unroll
    for (int i = 0; i < 2; i++)
        #pragma unroll
        for (int j = 0; j < 8; j++)
            #pragma unroll
            for (int q = 0; q < 4; q++) acc[i][j][q] = 0.f;

    // per-thread ldmatrix base offsets (within a stage)
    uint32_t a_off = (uint32_t)(mw * 32 + (lane & 15)) * ROWPITCH + (lane >> 4) * 16;
    uint32_t b_off = (uint32_t)(MT + nw * 64 + (lane & 15)) * ROWPITCH + (lane >> 4) * 16;

    // prologue: stages 0..2
    #pragma unroll
    for (int s = 0; s < STAGES - 1; s++) {
        load_stage(sb, s, s, m0, n0, tid);
        CP_COMMIT();
    }

    #pragma unroll 1
    for (int ch = 0; ch < NCH; ch++) {
        CP_WAIT(STAGES - 2);
        __syncthreads();

        // issue loads for chunk ch+3 (into the stage consumed at ch-1)
        if (ch + STAGES - 1 < NCH)
            load_stage(sb, (ch + STAGES - 1) & (STAGES - 1), ch + STAGES - 1,
                       m0, n0, tid);
        CP_COMMIT();

        uint32_t stb = sb + (ch & (STAGES - 1)) * STG;
        uint32_t ab = stb + a_off;
        uint32_t bb = stb + b_off;
        #pragma unroll
        for (int ks = 0; ks < 2; ks++) {
            uint32_t a0[4], a1[4];
            ldsm4(a0, ab + ks * 32);
            ldsm4(a1, ab + 16 * ROWPITCH + ks * 32);
            #pragma unroll
            for (int j = 0; j < 4; j++) {
                uint32_t b[4];
                ldsm4(b, bb + j * 16 * ROWPITCH + ks * 32);
                mma16816(acc[0][2 * j],     a0, b[0], b[2]);
                mma16816(acc[0][2 * j + 1], a0, b[1], b[3]);
                mma16816(acc[1][2 * j],     a1, b[0], b[2]);
                mma16816(acc[1][2 * j + 1], a1, b[1], b[3]);
            }
        }
    }

    // epilogue: add bias, store float2 pairs
    int l4 = lane >> 2;            // row 0..7 within 8
    int l2 = (lane & 3) * 2;       // col pair base
    #pragma unroll
    for (int im = 0; im < 2; im++) {
        int mbase = m0 + mw * 32 + im * 16 + l4;
        #pragma unroll
        for (int jn = 0; jn < 8; jn++) {
            int col = n0 + nw * 64 + jn * 8 + l2;
            float2 bv = *(const float2*)(bias + col);
            float2 v0, v1;
            v0.x = acc[im][jn][0] + bv.x;
            v0.y = acc[im][jn][1] + bv.y;
            v1.x = acc[im][jn][2] + bv.x;
            v1.y = acc[im][jn][3] + bv.y;
            *(float2*)(out + (size_t)mbase * OUTF + col) = v0;
            *(float2*)(out + (size_t)(mbase + 8) * OUTF + col) = v1;
        }
    }
}

// ---------------------------------------------------------------------------
extern "C" void kernel_launch(void* const* d_in, const int* in_sizes, int n_in,
                              void* d_out, int out_size) {
    const float* x    = (const float*)d_in[0];  // [8192, 4096] f32
    const float* w    = (const float*)d_in[1];  // [NNZ] f32
    const float* bias = (const float*)d_in[2];  // [4096] f32
    const void*  idx  = d_in[3];                // [2, NNZ] int64 or int32
    float* out = (float*)d_out;                 // [8192, 4096] f32
    int nnz = in_sizes[1];

    // Unconditional (no static guards); not a stream op -> capture-safe.
    cudaFuncSetAttribute(k_gemm, cudaFuncAttributeMaxDynamicSharedMemorySize,
                         SMEM_TOTAL);

    k_detect<<<1, 32>>>((const int*)idx);
    k_zero_wh<<<(int)((size_t)OUTF * INF / 8 / 256), 256>>>();
    k_scatter<<<(nnz + 255) / 256, 256>>>(idx, w, nnz);
    k_conv_x<<<(int)((size_t)NTOK * INF / 4 / 256), 256>>>(x);

    dim3 grid(OUTF / NTLE, NTOK / MT);   // (16, 64)
    k_gemm<<<grid, 512, SMEM_TOTAL>>>(bias, out);
}